// round 7
// baseline (speedup 1.0000x reference)
#include <cuda_runtime.h>
#include <math.h>

// S4 diagonal complex SSM scan, chunked 3-pass formulation.
// R7: pass1 k=8 step blocking (C_j = Lam^j dtB, 22 FFMA2 per 8 steps);
//     pass3 2-way state split (8 states/thread, NP=4, single shfl round),
//     transposed smem x tile, direct STG. pass2 unchanged.

#define LL 4096
#define DD 1024
#define NN 16
#define CC 64       // chunks
#define TT 64       // timesteps per chunk
#define DW 16       // d-channels per pass1 block (128 thr / 8 octs)
#define PAD 68      // padded row stride for smem x tiles
#define DW3 64      // d-channels per pass3 block (128 thr / 2 halves)

__device__ float g_S_re[CC * DD * NN];
__device__ float g_S_im[CC * DD * NN];

// ---------------- packed f32x2 helpers ----------------
struct f2 { unsigned long long v; };

__device__ __forceinline__ f2 f2pack(float lo, float hi) {
    f2 r; asm("mov.b64 %0, {%1, %2};" : "=l"(r.v) : "f"(lo), "f"(hi)); return r;
}
__device__ __forceinline__ void f2unpack(f2 a, float& lo, float& hi) {
    asm("mov.b64 {%0, %1}, %2;" : "=f"(lo), "=f"(hi) : "l"(a.v));
}
__device__ __forceinline__ f2 f2fma(f2 a, f2 b, f2 c) {
    f2 r; asm("fma.rn.f32x2 %0, %1, %2, %3;" : "=l"(r.v) : "l"(a.v), "l"(b.v), "l"(c.v)); return r;
}
__device__ __forceinline__ f2 f2mul(f2 a, f2 b) {
    f2 r; asm("mul.rn.f32x2 %0, %1, %2;" : "=l"(r.v) : "l"(a.v), "l"(b.v)); return r;
}
__device__ __forceinline__ f2 f2add(f2 a, f2 b) {
    f2 r; asm("add.rn.f32x2 %0, %1, %2;" : "=l"(r.v) : "l"(a.v), "l"(b.v)); return r;
}
__device__ __forceinline__ f2 f2zero() { f2 r; r.v = 0ull; return r; }

__device__ __forceinline__ float softplus_f(float v) {
    return (v > 20.0f) ? v : log1pf(expf(v));
}

__device__ __forceinline__ void lam_dn(float dt, float ar, float ai,
                                       float& lre, float& lim) {
    float m = expf(dt * ar);
    float s, c;
    sincosf(dt * ai, &s, &c);
    lre = m * c;
    lim = m * s;
}

// ---------------- pass 1: local chunk scans, k=8 step blocking --------------
__global__ void __launch_bounds__(128, 8)
s4_pass1(const float* __restrict__ x, const float* __restrict__ Delta,
         const float* __restrict__ A_re, const float* __restrict__ A_im,
         const float* __restrict__ B_re, const float* __restrict__ B_im) {
    __shared__ float xs_sm[DW * PAD];
    const int tid = threadIdx.x;
    const int dl  = tid >> 3;          // 0..15
    const int o   = tid & 7;           // oct -> 2 states
    const int d   = blockIdx.x * DW + dl;
    const int nb  = o * 2;
    const int c   = blockIdx.y;

    // coalesced transposed x tile load: xs_sm[d][t]
    {
        const float* xg = x + (size_t)c * TT * DD + blockIdx.x * DW;
        #pragma unroll
        for (int r = 0; r < 2; r++) {
            const int idx = tid + r * 128;     // 0..255 float4 slots
            const int t  = idx >> 2;           // 0..63
            const int dq = (idx & 3) * 4;      // 0,4,8,12
            float4 v = *(const float4*)&xg[t * DD + dq];
            xs_sm[(dq + 0) * PAD + t] = v.x;
            xs_sm[(dq + 1) * PAD + t] = v.y;
            xs_sm[(dq + 2) * PAD + t] = v.z;
            xs_sm[(dq + 3) * PAD + t] = v.w;
        }
    }

    const float dt = softplus_f(Delta[d]);
    const float2 ar2 = *(const float2*)&A_re[d * NN + nb];
    const float2 ai2 = *(const float2*)&A_im[d * NN + nb];
    const float2 br2 = *(const float2*)&B_re[d * NN + nb];
    const float2 bi2 = *(const float2*)&B_im[d * NN + nb];
    const float arr[2] = {ar2.x, ar2.y};
    const float aii[2] = {ai2.x, ai2.y};
    const float brr[2] = {br2.x, br2.y};
    const float bii[2] = {bi2.x, bi2.y};

    // C_j = Lam^j * dt*B, j=0..7 ; L8 = Lam^8
    float cr[8][2], ci[8][2], l8r[2], l8i[2];
    #pragma unroll
    for (int k = 0; k < 2; k++) {
        float lr, li;
        lam_dn(dt, arr[k], aii[k], lr, li);
        cr[0][k] = dt * brr[k];
        ci[0][k] = dt * bii[k];
        #pragma unroll
        for (int j = 1; j < 8; j++) {
            cr[j][k] = lr * cr[j-1][k] - li * ci[j-1][k];
            ci[j][k] = lr * ci[j-1][k] + li * cr[j-1][k];
        }
        float pr = lr, pi = li;
        #pragma unroll
        for (int s = 0; s < 3; s++) {
            const float nr = pr * pr - pi * pi;
            pi = 2.0f * pr * pi;
            pr = nr;
        }
        l8r[k] = pr; l8i[k] = pi;
    }

    f2 Cr[8], Ci[8];
    #pragma unroll
    for (int j = 0; j < 8; j++) {
        Cr[j] = f2pack(cr[j][0], cr[j][1]);
        Ci[j] = f2pack(ci[j][0], ci[j][1]);
    }
    const f2 L8re  = f2pack(l8r[0], l8r[1]);
    const f2 L8im  = f2pack(l8i[0], l8i[1]);
    const f2 nL8im = f2pack(-l8i[0], -l8i[1]);

    f2 hre = f2zero(), him = f2zero();

    __syncthreads();

    const float* xr = &xs_sm[dl * PAD];
    #pragma unroll 2
    for (int t = 0; t < TT; t += 8) {
        const float4 xa = *(const float4*)&xr[t];
        const float4 xb = *(const float4*)&xr[t + 4];
        const f2 x1 = f2pack(xa.x, xa.x), x2 = f2pack(xa.y, xa.y);
        const f2 x3 = f2pack(xa.z, xa.z), x4 = f2pack(xa.w, xa.w);
        const f2 x5 = f2pack(xb.x, xb.x), x6 = f2pack(xb.y, xb.y);
        const f2 x7 = f2pack(xb.z, xb.z), x8 = f2pack(xb.w, xb.w);
        // h_{t+8} = L8 h + C7 x1 + C6 x2 + ... + C0 x8
        f2 tr = f2fma(Cr[1], x7, f2mul(Cr[0], x8));
        tr = f2fma(Cr[2], x6, tr);
        tr = f2fma(Cr[3], x5, tr);
        tr = f2fma(Cr[4], x4, tr);
        tr = f2fma(Cr[5], x3, tr);
        tr = f2fma(Cr[6], x2, tr);
        tr = f2fma(Cr[7], x1, tr);
        f2 ti = f2fma(Ci[1], x7, f2mul(Ci[0], x8));
        ti = f2fma(Ci[2], x6, ti);
        ti = f2fma(Ci[3], x5, ti);
        ti = f2fma(Ci[4], x4, ti);
        ti = f2fma(Ci[5], x3, ti);
        ti = f2fma(Ci[6], x2, ti);
        ti = f2fma(Ci[7], x1, ti);
        f2 nr = f2fma(L8re, hre, f2fma(nL8im, him, tr));
        f2 ni = f2fma(L8re, him, f2fma(L8im,  hre, ti));
        hre = nr; him = ni;
    }

    float r0, r1, i0, i1;
    f2unpack(hre, r0, r1);
    f2unpack(him, i0, i1);
    const int base = (c * DD + d) * NN + nb;
    *(float2*)&g_S_re[base] = make_float2(r0, r1);
    *(float2*)&g_S_im[base] = make_float2(i0, i1);
}

// ---------------- pass 2: cross-chunk scan (ends -> inits, in place) --------
__global__ void __launch_bounds__(128)
s4_pass2(const float* __restrict__ Delta,
         const float* __restrict__ A_re, const float* __restrict__ A_im) {
    const int i = blockIdx.x * blockDim.x + threadIdx.x;  // i = d*NN + n
    const int d = i >> 4;

    const float dt = softplus_f(Delta[d]);
    float lr, li;
    lam_dn(dt, A_re[i], A_im[i], lr, li);
    #pragma unroll
    for (int s = 0; s < 6; s++) {   // Lam^64
        float nr = lr * lr - li * li;
        li = 2.0f * lr * li;
        lr = nr;
    }

    float er[8], ei[8];
    #pragma unroll
    for (int u = 0; u < 8; u++) {
        const int idx = u * (DD * NN) + i;
        er[u] = g_S_re[idx];
        ei[u] = g_S_im[idx];
    }

    float hr = 0.0f, hi = 0.0f;
    #pragma unroll 1
    for (int cb = 0; cb < CC; cb += 8) {
        const bool more = (cb + 8) < CC;
        float er2[8], ei2[8];
        #pragma unroll
        for (int u = 0; u < 8; u++) {
            const int idx = (cb + 8 + u) * (DD * NN) + i;
            er2[u] = more ? g_S_re[idx] : 0.0f;
            ei2[u] = more ? g_S_im[idx] : 0.0f;
        }
        #pragma unroll
        for (int u = 0; u < 8; u++) {
            const int idx = (cb + u) * (DD * NN) + i;
            g_S_re[idx] = hr;
            g_S_im[idx] = hi;
            const float tr = lr * hr - li * hi + er[u];
            hi = lr * hi + li * hr + ei[u];
            hr = tr;
        }
        #pragma unroll
        for (int u = 0; u < 8; u++) { er[u] = er2[u]; ei[u] = ei2[u]; }
    }
}

// ---------------- pass 3: full scan with init state, emit output ------------
// 2-way split: 8 states per thread (NP=4 pairs), one shfl round.
__global__ void __launch_bounds__(128, 7)
s4_pass3(const float* __restrict__ x, const float* __restrict__ Delta,
         const float* __restrict__ A_re, const float* __restrict__ A_im,
         const float* __restrict__ B_re, const float* __restrict__ B_im,
         const float* __restrict__ C_re, const float* __restrict__ C_im,
         const float* __restrict__ D_param, float* __restrict__ out) {
    __shared__ float xs_sm[DW3 * PAD];
    const int tid  = threadIdx.x;
    const int dl   = tid >> 1;         // 0..63
    const int half = tid & 1;
    const int d    = blockIdx.x * DW3 + dl;
    const int nb   = half * 8;
    const int c    = blockIdx.y;

    // coalesced transposed x tile load: xs_sm[d][t]  (64 d x 64 t)
    {
        const float* xg = x + (size_t)c * TT * DD + blockIdx.x * DW3;
        #pragma unroll
        for (int r = 0; r < 8; r++) {
            const int idx = tid + r * 128;     // 0..1023 float4 slots
            const int t  = idx >> 4;           // 0..63
            const int dq = (idx & 15) * 4;     // 0,4,..,60
            float4 v = *(const float4*)&xg[t * DD + dq];
            xs_sm[(dq + 0) * PAD + t] = v.x;
            xs_sm[(dq + 1) * PAD + t] = v.y;
            xs_sm[(dq + 2) * PAD + t] = v.z;
            xs_sm[(dq + 3) * PAD + t] = v.w;
        }
    }

    const float dt = softplus_f(Delta[d]);
    const float Dp = D_param[d];

    // per-thread 8 states: params via 2x float4 each
    float arr[8], aii[8], brr[8], bii[8], crr[8], cii[8], hrr[8], hii[8];
    {
        const int pb = d * NN + nb;
        const int sb = (c * DD + d) * NN + nb;
        #pragma unroll
        for (int g = 0; g < 2; g++) {
            const float4 a4 = *(const float4*)&A_re[pb + 4 * g];
            const float4 b4 = *(const float4*)&A_im[pb + 4 * g];
            const float4 c4 = *(const float4*)&B_re[pb + 4 * g];
            const float4 d4 = *(const float4*)&B_im[pb + 4 * g];
            const float4 e4 = *(const float4*)&C_re[pb + 4 * g];
            const float4 f4 = *(const float4*)&C_im[pb + 4 * g];
            const float4 g4 = *(const float4*)&g_S_re[sb + 4 * g];
            const float4 h4 = *(const float4*)&g_S_im[sb + 4 * g];
            arr[4*g+0]=a4.x; arr[4*g+1]=a4.y; arr[4*g+2]=a4.z; arr[4*g+3]=a4.w;
            aii[4*g+0]=b4.x; aii[4*g+1]=b4.y; aii[4*g+2]=b4.z; aii[4*g+3]=b4.w;
            brr[4*g+0]=c4.x; brr[4*g+1]=c4.y; brr[4*g+2]=c4.z; brr[4*g+3]=c4.w;
            bii[4*g+0]=d4.x; bii[4*g+1]=d4.y; bii[4*g+2]=d4.z; bii[4*g+3]=d4.w;
            crr[4*g+0]=e4.x; crr[4*g+1]=e4.y; crr[4*g+2]=e4.z; crr[4*g+3]=e4.w;
            cii[4*g+0]=f4.x; cii[4*g+1]=f4.y; cii[4*g+2]=f4.z; cii[4*g+3]=f4.w;
            hrr[4*g+0]=g4.x; hrr[4*g+1]=g4.y; hrr[4*g+2]=g4.z; hrr[4*g+3]=g4.w;
            hii[4*g+0]=h4.x; hii[4*g+1]=h4.y; hii[4*g+2]=h4.z; hii[4*g+3]=h4.w;
        }
    }

    // g = C (.) h: g' = Lam g + (C*dt*B) x, y = sum Re(g) over all n
    float lr[8], li[8], vr[8], vi[8], gr[8], gi[8];
    #pragma unroll
    for (int k = 0; k < 8; k++) {
        lam_dn(dt, arr[k], aii[k], lr[k], li[k]);
        const float br = dt * brr[k], bi = dt * bii[k];
        vr[k] = crr[k] * br - cii[k] * bi;
        vi[k] = crr[k] * bi + cii[k] * br;
        gr[k] = crr[k] * hrr[k] - cii[k] * hii[k];
        gi[k] = crr[k] * hii[k] + cii[k] * hrr[k];
    }

    f2 lre[4], lim[4], nlim[4], wre[4], wim[4], gre[4], gim[4];
    #pragma unroll
    for (int j = 0; j < 4; j++) {
        const int a = 2 * j, b = 2 * j + 1;
        lre[j]  = f2pack(lr[a], lr[b]);
        lim[j]  = f2pack(li[a], li[b]);
        nlim[j] = f2pack(-li[a], -li[b]);
        wre[j]  = f2pack(vr[a], vr[b]);
        wim[j]  = f2pack(vi[a], vi[b]);
        gre[j]  = f2pack(gr[a], gr[b]);
        gim[j]  = f2pack(gi[a], gi[b]);
    }

    __syncthreads();

    const float* xr = &xs_sm[dl * PAD];
    float* op = out + (size_t)c * TT * DD + d;

    #pragma unroll 1
    for (int tb = 0; tb < TT; tb += 8) {
        const float4 xa = *(const float4*)&xr[tb];
        const float4 xb = *(const float4*)&xr[tb + 4];
        const float xs[8] = {xa.x, xa.y, xa.z, xa.w, xb.x, xb.y, xb.z, xb.w};
        float ys[8];
        #pragma unroll
        for (int u = 0; u < 8; u++) {
            f2 x2 = f2pack(xs[u], xs[u]);
            #pragma unroll
            for (int j = 0; j < 4; j++) {
                f2 nr = f2fma(lre[j], gre[j], f2fma(nlim[j], gim[j], f2mul(wre[j], x2)));
                f2 ni = f2fma(lre[j], gim[j], f2fma(lim[j],  gre[j], f2mul(wim[j], x2)));
                gre[j] = nr; gim[j] = ni;
            }
            f2 s01 = f2add(gre[0], gre[1]);
            f2 s23 = f2add(gre[2], gre[3]);
            f2 s   = f2add(s01, s23);
            float lo, hi;
            f2unpack(s, lo, hi);
            ys[u] = lo + hi;
        }
        // combine the two half-threads (adjacent lanes), batched
        #pragma unroll
        for (int u = 0; u < 8; u++)
            ys[u] += __shfl_xor_sync(0xFFFFFFFFu, ys[u], 1);
        if (half == 0) {
            #pragma unroll
            for (int u = 0; u < 8; u++)
                op[(tb + u) * DD] = ys[u] + Dp * xs[u];
        }
    }
}

extern "C" void kernel_launch(void* const* d_in, const int* in_sizes, int n_in,
                              void* d_out, int out_size) {
    const float* x     = (const float*)d_in[0];
    const float* Delta = (const float*)d_in[1];
    const float* A_re  = (const float*)d_in[2];
    const float* A_im  = (const float*)d_in[3];
    const float* B_re  = (const float*)d_in[4];
    const float* B_im  = (const float*)d_in[5];
    const float* C_re  = (const float*)d_in[6];
    const float* C_im  = (const float*)d_in[7];
    const float* Dp    = (const float*)d_in[8];
    float* out = (float*)d_out;

    dim3 blk(128);
    s4_pass1<<<dim3(DD / DW,  CC), blk>>>(x, Delta, A_re, A_im, B_re, B_im);
    s4_pass2<<<(DD * NN) / 128, blk>>>(Delta, A_re, A_im);
    s4_pass3<<<dim3(DD / DW3, CC), blk>>>(x, Delta, A_re, A_im, B_re, B_im,
                                          C_re, C_im, Dp, out);
}

// round 8
// speedup vs baseline: 1.0993x; 1.0993x over previous
#include <cuda_runtime.h>
#include <math.h>

// S4 diagonal complex SSM scan, chunked 3-pass formulation.
// R8: chunk batching to amortize transcendental setup — pass1 does 4 chunks
//     per block (one coefficient computation), pass3 does 2. pass1 keeps the
//     k=8 step blocking + 8-way split; pass3 back to 4-way split (R5 sweet
//     spot) with transposed padded smem tile (LDS.128) + batched shfl.

#define LL 4096
#define DD 1024
#define NN 16
#define CC 64       // chunks
#define TT 64       // timesteps per chunk
#define DW 16       // d-channels per pass1 block (128 thr / 8 octs)
#define PAD 68      // padded row stride for smem x tiles
#define DW3 32      // d-channels per pass3 block (128 thr / 4 quarters)
#define CB1 4       // chunks per pass1 block
#define CB3 2       // chunks per pass3 block

__device__ float g_S_re[CC * DD * NN];
__device__ float g_S_im[CC * DD * NN];

// ---------------- packed f32x2 helpers ----------------
struct f2 { unsigned long long v; };

__device__ __forceinline__ f2 f2pack(float lo, float hi) {
    f2 r; asm("mov.b64 %0, {%1, %2};" : "=l"(r.v) : "f"(lo), "f"(hi)); return r;
}
__device__ __forceinline__ void f2unpack(f2 a, float& lo, float& hi) {
    asm("mov.b64 {%0, %1}, %2;" : "=f"(lo), "=f"(hi) : "l"(a.v));
}
__device__ __forceinline__ f2 f2fma(f2 a, f2 b, f2 c) {
    f2 r; asm("fma.rn.f32x2 %0, %1, %2, %3;" : "=l"(r.v) : "l"(a.v), "l"(b.v), "l"(c.v)); return r;
}
__device__ __forceinline__ f2 f2mul(f2 a, f2 b) {
    f2 r; asm("mul.rn.f32x2 %0, %1, %2;" : "=l"(r.v) : "l"(a.v), "l"(b.v)); return r;
}
__device__ __forceinline__ f2 f2add(f2 a, f2 b) {
    f2 r; asm("add.rn.f32x2 %0, %1, %2;" : "=l"(r.v) : "l"(a.v), "l"(b.v)); return r;
}
__device__ __forceinline__ f2 f2zero() { f2 r; r.v = 0ull; return r; }

__device__ __forceinline__ float softplus_f(float v) {
    return (v > 20.0f) ? v : log1pf(expf(v));
}

__device__ __forceinline__ void lam_dn(float dt, float ar, float ai,
                                       float& lre, float& lim) {
    float m = expf(dt * ar);
    float s, c;
    sincosf(dt * ai, &s, &c);
    lre = m * c;
    lim = m * s;
}

// ---------------- pass 1: local chunk scans, k=8 blocking, 4 chunks/block ---
__global__ void __launch_bounds__(128, 8)
s4_pass1(const float* __restrict__ x, const float* __restrict__ Delta,
         const float* __restrict__ A_re, const float* __restrict__ A_im,
         const float* __restrict__ B_re, const float* __restrict__ B_im) {
    __shared__ float xs_sm[DW * PAD];
    const int tid = threadIdx.x;
    const int dl  = tid >> 3;          // 0..15
    const int o   = tid & 7;           // oct -> 2 states
    const int d   = blockIdx.x * DW + dl;
    const int nb  = o * 2;
    const int c0  = blockIdx.y * CB1;

    // ---- one-time coefficient setup (amortized over CB1 chunks) ----
    const float dt = softplus_f(Delta[d]);
    const float2 ar2 = *(const float2*)&A_re[d * NN + nb];
    const float2 ai2 = *(const float2*)&A_im[d * NN + nb];
    const float2 br2 = *(const float2*)&B_re[d * NN + nb];
    const float2 bi2 = *(const float2*)&B_im[d * NN + nb];
    const float arr[2] = {ar2.x, ar2.y};
    const float aii[2] = {ai2.x, ai2.y};
    const float brr[2] = {br2.x, br2.y};
    const float bii[2] = {bi2.x, bi2.y};

    // C_j = Lam^j * dt*B, j=0..7 ; L8 = Lam^8
    float cr[8][2], ci[8][2], l8r[2], l8i[2];
    #pragma unroll
    for (int k = 0; k < 2; k++) {
        float lr, li;
        lam_dn(dt, arr[k], aii[k], lr, li);
        cr[0][k] = dt * brr[k];
        ci[0][k] = dt * bii[k];
        #pragma unroll
        for (int j = 1; j < 8; j++) {
            cr[j][k] = lr * cr[j-1][k] - li * ci[j-1][k];
            ci[j][k] = lr * ci[j-1][k] + li * cr[j-1][k];
        }
        float pr = lr, pi = li;
        #pragma unroll
        for (int s = 0; s < 3; s++) {
            const float nr = pr * pr - pi * pi;
            pi = 2.0f * pr * pi;
            pr = nr;
        }
        l8r[k] = pr; l8i[k] = pi;
    }

    f2 Cr[8], Ci[8];
    #pragma unroll
    for (int j = 0; j < 8; j++) {
        Cr[j] = f2pack(cr[j][0], cr[j][1]);
        Ci[j] = f2pack(ci[j][0], ci[j][1]);
    }
    const f2 L8re  = f2pack(l8r[0], l8r[1]);
    const f2 L8im  = f2pack(l8i[0], l8i[1]);
    const f2 nL8im = f2pack(-l8i[0], -l8i[1]);

    const float* xr = &xs_sm[dl * PAD];

    #pragma unroll 1
    for (int u = 0; u < CB1; u++) {
        const int c = c0 + u;
        __syncthreads();   // protect previous tile reads
        // coalesced transposed x tile load: xs_sm[d][t]
        {
            const float* xg = x + (size_t)c * TT * DD + blockIdx.x * DW;
            #pragma unroll
            for (int r = 0; r < 2; r++) {
                const int idx = tid + r * 128;
                const int t  = idx >> 2;
                const int dq = (idx & 3) * 4;
                float4 v = *(const float4*)&xg[t * DD + dq];
                xs_sm[(dq + 0) * PAD + t] = v.x;
                xs_sm[(dq + 1) * PAD + t] = v.y;
                xs_sm[(dq + 2) * PAD + t] = v.z;
                xs_sm[(dq + 3) * PAD + t] = v.w;
            }
        }
        __syncthreads();

        f2 hre = f2zero(), him = f2zero();
        #pragma unroll 2
        for (int t = 0; t < TT; t += 8) {
            const float4 xa = *(const float4*)&xr[t];
            const float4 xb = *(const float4*)&xr[t + 4];
            const f2 x1 = f2pack(xa.x, xa.x), x2 = f2pack(xa.y, xa.y);
            const f2 x3 = f2pack(xa.z, xa.z), x4 = f2pack(xa.w, xa.w);
            const f2 x5 = f2pack(xb.x, xb.x), x6 = f2pack(xb.y, xb.y);
            const f2 x7 = f2pack(xb.z, xb.z), x8 = f2pack(xb.w, xb.w);
            f2 tr = f2fma(Cr[1], x7, f2mul(Cr[0], x8));
            tr = f2fma(Cr[2], x6, tr);
            tr = f2fma(Cr[3], x5, tr);
            tr = f2fma(Cr[4], x4, tr);
            tr = f2fma(Cr[5], x3, tr);
            tr = f2fma(Cr[6], x2, tr);
            tr = f2fma(Cr[7], x1, tr);
            f2 ti = f2fma(Ci[1], x7, f2mul(Ci[0], x8));
            ti = f2fma(Ci[2], x6, ti);
            ti = f2fma(Ci[3], x5, ti);
            ti = f2fma(Ci[4], x4, ti);
            ti = f2fma(Ci[5], x3, ti);
            ti = f2fma(Ci[6], x2, ti);
            ti = f2fma(Ci[7], x1, ti);
            f2 nr = f2fma(L8re, hre, f2fma(nL8im, him, tr));
            f2 ni = f2fma(L8re, him, f2fma(L8im,  hre, ti));
            hre = nr; him = ni;
        }

        float r0, r1, i0, i1;
        f2unpack(hre, r0, r1);
        f2unpack(him, i0, i1);
        const int base = (c * DD + d) * NN + nb;
        *(float2*)&g_S_re[base] = make_float2(r0, r1);
        *(float2*)&g_S_im[base] = make_float2(i0, i1);
    }
}

// ---------------- pass 2: cross-chunk scan (ends -> inits, in place) --------
__global__ void __launch_bounds__(128)
s4_pass2(const float* __restrict__ Delta,
         const float* __restrict__ A_re, const float* __restrict__ A_im) {
    const int i = blockIdx.x * blockDim.x + threadIdx.x;  // i = d*NN + n
    const int d = i >> 4;

    const float dt = softplus_f(Delta[d]);
    float lr, li;
    lam_dn(dt, A_re[i], A_im[i], lr, li);
    #pragma unroll
    for (int s = 0; s < 6; s++) {   // Lam^64
        float nr = lr * lr - li * li;
        li = 2.0f * lr * li;
        lr = nr;
    }

    float er[8], ei[8];
    #pragma unroll
    for (int u = 0; u < 8; u++) {
        const int idx = u * (DD * NN) + i;
        er[u] = g_S_re[idx];
        ei[u] = g_S_im[idx];
    }

    float hr = 0.0f, hi = 0.0f;
    #pragma unroll 1
    for (int cb = 0; cb < CC; cb += 8) {
        const bool more = (cb + 8) < CC;
        float er2[8], ei2[8];
        #pragma unroll
        for (int u = 0; u < 8; u++) {
            const int idx = (cb + 8 + u) * (DD * NN) + i;
            er2[u] = more ? g_S_re[idx] : 0.0f;
            ei2[u] = more ? g_S_im[idx] : 0.0f;
        }
        #pragma unroll
        for (int u = 0; u < 8; u++) {
            const int idx = (cb + u) * (DD * NN) + i;
            g_S_re[idx] = hr;
            g_S_im[idx] = hi;
            const float tr = lr * hr - li * hi + er[u];
            hi = lr * hi + li * hr + ei[u];
            hr = tr;
        }
        #pragma unroll
        for (int u = 0; u < 8; u++) { er[u] = er2[u]; ei[u] = ei2[u]; }
    }
}

// ---------------- pass 3: full scan, 4-way split, 2 chunks/block ------------
__global__ void __launch_bounds__(128, 8)
s4_pass3(const float* __restrict__ x, const float* __restrict__ Delta,
         const float* __restrict__ A_re, const float* __restrict__ A_im,
         const float* __restrict__ B_re, const float* __restrict__ B_im,
         const float* __restrict__ C_re, const float* __restrict__ C_im,
         const float* __restrict__ D_param, float* __restrict__ out) {
    __shared__ float xs_sm[DW3 * PAD];
    const int tid = threadIdx.x;
    const int dl  = tid >> 2;          // 0..31
    const int q   = tid & 3;
    const int d   = blockIdx.x * DW3 + dl;
    const int nb  = q * 4;
    const int c0  = blockIdx.y * CB3;

    // ---- one-time setup (amortized over CB3 chunks) ----
    const float dt = softplus_f(Delta[d]);
    const float Dp = D_param[d];

    const float4 ar4 = *(const float4*)&A_re[d * NN + nb];
    const float4 ai4 = *(const float4*)&A_im[d * NN + nb];
    const float4 br4 = *(const float4*)&B_re[d * NN + nb];
    const float4 bi4 = *(const float4*)&B_im[d * NN + nb];
    const float4 cr4 = *(const float4*)&C_re[d * NN + nb];
    const float4 ci4 = *(const float4*)&C_im[d * NN + nb];

    const float arr[4] = {ar4.x, ar4.y, ar4.z, ar4.w};
    const float aii[4] = {ai4.x, ai4.y, ai4.z, ai4.w};
    const float brr[4] = {br4.x, br4.y, br4.z, br4.w};
    const float bii[4] = {bi4.x, bi4.y, bi4.z, bi4.w};
    const float crr[4] = {cr4.x, cr4.y, cr4.z, cr4.w};
    const float cii[4] = {ci4.x, ci4.y, ci4.z, ci4.w};

    float lr[4], li[4], vr[4], vi[4];
    #pragma unroll
    for (int k = 0; k < 4; k++) {
        lam_dn(dt, arr[k], aii[k], lr[k], li[k]);
        const float br = dt * brr[k], bi = dt * bii[k];
        vr[k] = crr[k] * br - cii[k] * bi;
        vi[k] = crr[k] * bi + cii[k] * br;
    }

    f2 lre[2], lim[2], nlim[2], wre[2], wim[2];
    lre[0]  = f2pack(lr[0], lr[1]);   lre[1]  = f2pack(lr[2], lr[3]);
    lim[0]  = f2pack(li[0], li[1]);   lim[1]  = f2pack(li[2], li[3]);
    nlim[0] = f2pack(-li[0], -li[1]); nlim[1] = f2pack(-li[2], -li[3]);
    wre[0]  = f2pack(vr[0], vr[1]);   wre[1]  = f2pack(vr[2], vr[3]);
    wim[0]  = f2pack(vi[0], vi[1]);   wim[1]  = f2pack(vi[2], vi[3]);

    const float* xr = &xs_sm[dl * PAD];

    #pragma unroll 1
    for (int u = 0; u < CB3; u++) {
        const int c = c0 + u;
        __syncthreads();
        // coalesced transposed x tile load: xs_sm[d][t] (32 d x 64 t)
        {
            const float* xg = x + (size_t)c * TT * DD + blockIdx.x * DW3;
            #pragma unroll
            for (int r = 0; r < 4; r++) {
                const int idx = tid + r * 128;     // 0..511 float4 slots
                const int t  = idx >> 3;           // 0..63
                const int dq = (idx & 7) * 4;      // 0,4,..,28
                float4 v = *(const float4*)&xg[t * DD + dq];
                xs_sm[(dq + 0) * PAD + t] = v.x;
                xs_sm[(dq + 1) * PAD + t] = v.y;
                xs_sm[(dq + 2) * PAD + t] = v.z;
                xs_sm[(dq + 3) * PAD + t] = v.w;
            }
        }
        __syncthreads();

        // per-chunk init state, C folded in: g = C (.) h
        const int base = (c * DD + d) * NN + nb;
        const float4 h0r4 = *(const float4*)&g_S_re[base];
        const float4 h0i4 = *(const float4*)&g_S_im[base];
        const float hrr[4] = {h0r4.x, h0r4.y, h0r4.z, h0r4.w};
        const float hii[4] = {h0i4.x, h0i4.y, h0i4.z, h0i4.w};
        float gr[4], gi[4];
        #pragma unroll
        for (int k = 0; k < 4; k++) {
            gr[k] = crr[k] * hrr[k] - cii[k] * hii[k];
            gi[k] = crr[k] * hii[k] + cii[k] * hrr[k];
        }
        f2 gre[2], gim[2];
        gre[0] = f2pack(gr[0], gr[1]); gre[1] = f2pack(gr[2], gr[3]);
        gim[0] = f2pack(gi[0], gi[1]); gim[1] = f2pack(gi[2], gi[3]);

        float* op = out + (size_t)c * TT * DD + d;

        #pragma unroll 1
        for (int tb = 0; tb < TT; tb += 8) {
            const float4 xa = *(const float4*)&xr[tb];
            const float4 xb = *(const float4*)&xr[tb + 4];
            const float xs[8] = {xa.x, xa.y, xa.z, xa.w, xb.x, xb.y, xb.z, xb.w};
            float ys[8];
            #pragma unroll
            for (int w = 0; w < 8; w++) {
                f2 x2 = f2pack(xs[w], xs[w]);
                #pragma unroll
                for (int j = 0; j < 2; j++) {
                    f2 nr = f2fma(lre[j], gre[j], f2fma(nlim[j], gim[j], f2mul(wre[j], x2)));
                    f2 ni = f2fma(lre[j], gim[j], f2fma(lim[j],  gre[j], f2mul(wim[j], x2)));
                    gre[j] = nr; gim[j] = ni;
                }
                f2 s = f2add(gre[0], gre[1]);
                float lo, hi;
                f2unpack(s, lo, hi);
                ys[w] = lo + hi;
            }
            #pragma unroll
            for (int w = 0; w < 8; w++)
                ys[w] += __shfl_xor_sync(0xFFFFFFFFu, ys[w], 1);
            #pragma unroll
            for (int w = 0; w < 8; w++)
                ys[w] += __shfl_xor_sync(0xFFFFFFFFu, ys[w], 2);
            if (q == 0) {
                #pragma unroll
                for (int w = 0; w < 8; w++)
                    op[(tb + w) * DD] = ys[w] + Dp * xs[w];
            }
        }
    }
}

extern "C" void kernel_launch(void* const* d_in, const int* in_sizes, int n_in,
                              void* d_out, int out_size) {
    const float* x     = (const float*)d_in[0];
    const float* Delta = (const float*)d_in[1];
    const float* A_re  = (const float*)d_in[2];
    const float* A_im  = (const float*)d_in[3];
    const float* B_re  = (const float*)d_in[4];
    const float* B_im  = (const float*)d_in[5];
    const float* C_re  = (const float*)d_in[6];
    const float* C_im  = (const float*)d_in[7];
    const float* Dp    = (const float*)d_in[8];
    float* out = (float*)d_out;

    dim3 blk(128);
    s4_pass1<<<dim3(DD / DW,  CC / CB1), blk>>>(x, Delta, A_re, A_im, B_re, B_im);
    s4_pass2<<<(DD * NN) / 128, blk>>>(Delta, A_re, A_im);
    s4_pass3<<<dim3(DD / DW3, CC / CB3), blk>>>(x, Delta, A_re, A_im, B_re, B_im,
                                                C_re, C_im, Dp, out);
}